// round 9
// baseline (speedup 1.0000x reference)
#include <cuda_runtime.h>
#include <cstdint>

// FeatureSim: attn[b,i,j] = softmax_j( masked(-sum_f |x[b,i,f]-x[b,j,f]| * w[f]) )
// B=8, N=1024, D=64, NF=11.
// Kernel 1: transpose x[:,:,:11] -> SoA planes g_xt[f][b*N + row]
// Kernel 2: BDIM=512, 2 j-cols/thread, R=8 rows/CTA, launch_bounds(512,2)
//           -> ~64 regs, 32 warps/SM (2x occupancy vs R8/256t/4j version).
//           Softmax without max-pass (valid scores in (-1,0], exp-safe;
//           invalid j -> exp(-1e9) == 0).

static constexpr int B_ = 8;
static constexpr int N_ = 1024;
static constexpr int D_ = 64;
static constexpr int NF = 11;
static constexpr int BN = B_ * N_;   // 8192
static constexpr int R = 8;
#define BDIM 512
#define NW   (BDIM / 32)             // 16 warps

__device__ float g_xt[NF * BN];   // 352 KB scratch, feature-major (SoA)

__global__ void transpose_kernel(const float* __restrict__ x) {
    int row = blockIdx.x * blockDim.x + threadIdx.x;   // 0 .. 8191
    if (row >= BN) return;
    const float4* p = reinterpret_cast<const float4*>(x + (size_t)row * D_);
    float4 a = p[0], b4 = p[1], c = p[2];
    float v[12];
    v[0] = a.x;  v[1] = a.y;  v[2]  = a.z;  v[3]  = a.w;
    v[4] = b4.x; v[5] = b4.y; v[6]  = b4.z; v[7]  = b4.w;
    v[8] = c.x;  v[9] = c.y;  v[10] = c.z;  v[11] = c.w;
#pragma unroll
    for (int f = 0; f < NF; f++)
        g_xt[f * BN + row] = v[f];     // coalesced across threads per plane
}

__global__ __launch_bounds__(BDIM, 2) void featuresim_kernel(
    const int*   __restrict__ xlen,     // (B,)
    const float* __restrict__ fimp,     // (NF,)
    float*       __restrict__ out)      // (B,N,N)
{
    const int b    = blockIdx.y;
    const int i0   = blockIdx.x * R;
    const int tid  = threadIdx.x;
    const int lane = tid & 31;
    const int wid  = tid >> 5;

    const int base = b * N_;
    const int len  = xlen[b];
    const int j0   = tid * 2;

    float w[NF];
#pragma unroll
    for (int f = 0; f < NF; f++) w[f] = __ldg(fimp + f);

    // j-features, SoA: one float2 per feature; consecutive lanes read
    // consecutive float2s -> fully coalesced. Reused across all R rows.
    float2 rjf[NF];
#pragma unroll
    for (int f = 0; f < NF; f++)
        rjf[f] = *reinterpret_cast<const float2*>(g_xt + f * BN + base + j0);

    const bool val0 = (j0 + 0) < len;
    const bool val1 = (j0 + 1) < len;

    __shared__ float reds[R][NW];

    float e[R][2];
#pragma unroll
    for (int r = 0; r < R; r++) {
        // i-row features: uniform broadcast loads
        float xi[NF];
#pragma unroll
        for (int f = 0; f < NF; f++)
            xi[f] = g_xt[f * BN + base + i0 + r];

        float s0 = 0.f, s1 = 0.f;
#pragma unroll
        for (int f = 0; f < NF; f++) {
            const float xif = xi[f];
            const float wf  = w[f];
            s0 = fmaf(fabsf(rjf[f].x - xif), wf, s0);
            s1 = fmaf(fabsf(rjf[f].y - xif), wf, s1);
        }
        float t0 = (s0 < 1.0f) ? -s0 : 0.0f;
        float t1 = (s1 < 1.0f) ? -s1 : 0.0f;

        // No max-pass: valid scores bounded in (-1, 0]; invalid -> exact 0.
        e[r][0] = __expf(val0 ? t0 : -1.0e9f);
        e[r][1] = __expf(val1 ? t1 : -1.0e9f);

        float ps = e[r][0] + e[r][1];
#pragma unroll
        for (int o = 16; o > 0; o >>= 1)
            ps += __shfl_xor_sync(0xFFFFFFFFu, ps, o);
        if (lane == 0) reds[r][wid] = ps;
    }
    __syncthreads();

#pragma unroll
    for (int r = 0; r < R; r++) {
        float t = reds[r][0];
#pragma unroll
        for (int k = 1; k < NW; k++) t += reds[r][k];
        const float inv = 1.0f / t;
        float2 o2;
        o2.x = e[r][0] * inv;
        o2.y = e[r][1] * inv;
        *reinterpret_cast<float2*>(out + ((size_t)(b * N_ + i0 + r)) * N_ + j0) = o2;
    }
}

extern "C" void kernel_launch(void* const* d_in, const int* in_sizes, int n_in,
                              void* d_out, int out_size)
{
    const float* x    = (const float*)d_in[0];
    const int*   xlen = (const int*)d_in[1];
    const float* fimp = (const float*)d_in[2];
    float*       out  = (float*)d_out;

    transpose_kernel<<<(BN + 255) / 256, 256>>>(x);
    dim3 grid(N_ / R, B_);
    featuresim_kernel<<<grid, BDIM>>>(xlen, fimp, out);
}

// round 11
// speedup vs baseline: 1.2270x; 1.2270x over previous
#include <cuda_runtime.h>
#include <cstdint>

// FeatureSim: attn[b,i,j] = softmax_j( masked(-sum_f |x[b,i,f]-x[b,j,f]| * w[f]) )
// B=8, N=1024, D=64, NF=11.
// Kernel 1: transpose x[:,:,:11] -> SoA planes g_xt[f][b*N + row]
// Kernel 2: 256 threads x 4 j-cols, R=8 rows/CTA. e[] staged in SMEM (private
//           per-thread slots, no extra sync) to cut register demand ->
//           launch_bounds(256,3) = 3 CTAs/SM (24 warps) vs 2 at 128 regs.
//           Softmax without max-pass (valid scores in (-1,0], exp-safe;
//           invalid j -> exp(-1e9) == 0).
// (Resubmission — round 10 died on container-acquisition infra, source never ran.)

static constexpr int B_ = 8;
static constexpr int N_ = 1024;
static constexpr int D_ = 64;
static constexpr int NF = 11;
static constexpr int BN = B_ * N_;   // 8192
static constexpr int R = 8;
#define BDIM 256
#define NW   (BDIM / 32)             // 8 warps

__device__ float g_xt[NF * BN];   // 352 KB scratch, feature-major (SoA)

__global__ void transpose_kernel(const float* __restrict__ x) {
    int row = blockIdx.x * blockDim.x + threadIdx.x;   // 0 .. 8191
    if (row >= BN) return;
    const float4* p = reinterpret_cast<const float4*>(x + (size_t)row * D_);
    float4 a = p[0], b4 = p[1], c = p[2];
    float v[12];
    v[0] = a.x;  v[1] = a.y;  v[2]  = a.z;  v[3]  = a.w;
    v[4] = b4.x; v[5] = b4.y; v[6]  = b4.z; v[7]  = b4.w;
    v[8] = c.x;  v[9] = c.y;  v[10] = c.z;  v[11] = c.w;
#pragma unroll
    for (int f = 0; f < NF; f++)
        g_xt[f * BN + row] = v[f];     // coalesced across threads per plane
}

__global__ __launch_bounds__(BDIM, 3) void featuresim_kernel(
    const int*   __restrict__ xlen,     // (B,)
    const float* __restrict__ fimp,     // (NF,)
    float*       __restrict__ out)      // (B,N,N)
{
    const int b    = blockIdx.y;
    const int i0   = blockIdx.x * R;
    const int tid  = threadIdx.x;
    const int lane = tid & 31;
    const int wid  = tid >> 5;

    const int base = b * N_;
    const int len  = xlen[b];
    const int j0   = tid * 4;

    // e staged in smem: private per-thread float4 slot per r (no sync needed
    // between write and read — same thread). 8 * 256 * 16B = 32 KB.
    __shared__ float4 s_e[R][BDIM];
    __shared__ float  reds[R][NW];

    float w[NF];
#pragma unroll
    for (int f = 0; f < NF; f++) w[f] = __ldg(fimp + f);

    // j-row features, SoA: one float4 per feature, fully coalesced across lanes.
    // Reused across all R rows.
    float4 rjf[NF];
#pragma unroll
    for (int f = 0; f < NF; f++)
        rjf[f] = *reinterpret_cast<const float4*>(g_xt + f * BN + base + j0);

    const bool val0 = (j0 + 0) < len;
    const bool val1 = (j0 + 1) < len;
    const bool val2 = (j0 + 2) < len;
    const bool val3 = (j0 + 3) < len;

#pragma unroll
    for (int r = 0; r < R; r++) {
        // i-row features: uniform broadcast loads (L1 hits)
        float xi[NF];
#pragma unroll
        for (int f = 0; f < NF; f++)
            xi[f] = g_xt[f * BN + base + i0 + r];

        float s0 = 0.f, s1 = 0.f, s2 = 0.f, s3 = 0.f;
#pragma unroll
        for (int f = 0; f < NF; f++) {
            const float xif = xi[f];
            const float wf  = w[f];
            s0 = fmaf(fabsf(rjf[f].x - xif), wf, s0);
            s1 = fmaf(fabsf(rjf[f].y - xif), wf, s1);
            s2 = fmaf(fabsf(rjf[f].z - xif), wf, s2);
            s3 = fmaf(fabsf(rjf[f].w - xif), wf, s3);
        }
        float t0 = (s0 < 1.0f) ? -s0 : 0.0f;
        float t1 = (s1 < 1.0f) ? -s1 : 0.0f;
        float t2 = (s2 < 1.0f) ? -s2 : 0.0f;
        float t3 = (s3 < 1.0f) ? -s3 : 0.0f;

        // No max-pass: valid scores bounded in (-1, 0]; invalid -> exact 0.
        float4 e4;
        e4.x = __expf(val0 ? t0 : -1.0e9f);
        e4.y = __expf(val1 ? t1 : -1.0e9f);
        e4.z = __expf(val2 ? t2 : -1.0e9f);
        e4.w = __expf(val3 ? t3 : -1.0e9f);
        s_e[r][tid] = e4;                       // stage in smem, frees registers

        float ps = (e4.x + e4.y) + (e4.z + e4.w);
#pragma unroll
        for (int o = 16; o > 0; o >>= 1)
            ps += __shfl_xor_sync(0xFFFFFFFFu, ps, o);
        if (lane == 0) reds[r][wid] = ps;
    }
    __syncthreads();

#pragma unroll
    for (int r = 0; r < R; r++) {
        float t = reds[r][0];
#pragma unroll
        for (int k = 1; k < NW; k++) t += reds[r][k];
        const float inv = 1.0f / t;
        float4 e4 = s_e[r][tid];
        float4 o4;
        o4.x = e4.x * inv;
        o4.y = e4.y * inv;
        o4.z = e4.z * inv;
        o4.w = e4.w * inv;
        *reinterpret_cast<float4*>(out + ((size_t)(b * N_ + i0 + r)) * N_ + j0) = o4;
    }
}

extern "C" void kernel_launch(void* const* d_in, const int* in_sizes, int n_in,
                              void* d_out, int out_size)
{
    const float* x    = (const float*)d_in[0];
    const int*   xlen = (const int*)d_in[1];
    const float* fimp = (const float*)d_in[2];
    float*       out  = (float*)d_out;

    transpose_kernel<<<(BN + 255) / 256, 256>>>(x);
    dim3 grid(N_ / R, B_);
    featuresim_kernel<<<grid, BDIM>>>(xlen, fimp, out);
}

// round 12
// speedup vs baseline: 1.3390x; 1.0913x over previous
#include <cuda_runtime.h>
#include <cstdint>

// FeatureSim: attn[b,i,j] = softmax_j( masked(-sum_f |x[b,i,f]-x[b,j,f]| * w[f]) )
// B=8, N=1024, D=64, NF=11.
// Kernel 1: transpose x[:,:,:11] -> SoA planes g_xt[f][b*N + row]
// Kernel 2: f-major inner loop with 32 persistent accumulators:
//           per feature: 1 coalesced LDG.128 (j-quad) + 2 broadcast LDG.128
//           (8 contiguous i-rows). Register demand ~60 -> launch_bounds(256,4)
//           = 4 CTAs/SM. e[] staged in private smem slots (no extra sync).
//           Softmax without max-pass (valid scores in (-1,0], exp-safe;
//           invalid j -> exp(-1e9) == 0).

static constexpr int B_ = 8;
static constexpr int N_ = 1024;
static constexpr int D_ = 64;
static constexpr int NF = 11;
static constexpr int BN = B_ * N_;   // 8192
static constexpr int R = 8;
#define BDIM 256
#define NW   (BDIM / 32)             // 8 warps

__device__ float g_xt[NF * BN];   // 352 KB scratch, feature-major (SoA)

__global__ void transpose_kernel(const float* __restrict__ x) {
    int row = blockIdx.x * blockDim.x + threadIdx.x;   // 0 .. 8191
    if (row >= BN) return;
    const float4* p = reinterpret_cast<const float4*>(x + (size_t)row * D_);
    float4 a = p[0], b4 = p[1], c = p[2];
    float v[12];
    v[0] = a.x;  v[1] = a.y;  v[2]  = a.z;  v[3]  = a.w;
    v[4] = b4.x; v[5] = b4.y; v[6]  = b4.z; v[7]  = b4.w;
    v[8] = c.x;  v[9] = c.y;  v[10] = c.z;  v[11] = c.w;
#pragma unroll
    for (int f = 0; f < NF; f++)
        g_xt[f * BN + row] = v[f];     // coalesced across threads per plane
}

__global__ __launch_bounds__(BDIM, 4) void featuresim_kernel(
    const int*   __restrict__ xlen,     // (B,)
    const float* __restrict__ fimp,     // (NF,)
    float*       __restrict__ out)      // (B,N,N)
{
    const int b    = blockIdx.y;
    const int i0   = blockIdx.x * R;
    const int tid  = threadIdx.x;
    const int lane = tid & 31;
    const int wid  = tid >> 5;

    const int base = b * N_;
    const int len  = xlen[b];
    const int j0   = tid * 4;

    // e staged in smem: private per-thread float4 slot per r.
    __shared__ float4 s_e[R][BDIM];      // 32 KB
    __shared__ float  reds[R][NW];

    const float* pj = g_xt + base + j0;   // this thread's j-quad base
    const float* pi = g_xt + base + i0;   // CTA's 8 i-rows base (uniform)

    // 32 persistent accumulators: acc[r][c]
    float acc[R][4];
#pragma unroll
    for (int r = 0; r < R; r++) {
        acc[r][0] = 0.f; acc[r][1] = 0.f; acc[r][2] = 0.f; acc[r][3] = 0.f;
    }

#pragma unroll
    for (int f = 0; f < NF; f++) {
        const float  wf  = __ldg(fimp + f);
        const float4 xj  = *reinterpret_cast<const float4*>(pj + f * BN);
        const float4 xiA = *reinterpret_cast<const float4*>(pi + f * BN);      // rows 0..3
        const float4 xiB = *reinterpret_cast<const float4*>(pi + f * BN + 4);  // rows 4..7
        const float xiv[8] = { xiA.x, xiA.y, xiA.z, xiA.w,
                               xiB.x, xiB.y, xiB.z, xiB.w };
#pragma unroll
        for (int r = 0; r < R; r++) {
            const float xv = xiv[r];
            acc[r][0] = fmaf(fabsf(xj.x - xv), wf, acc[r][0]);
            acc[r][1] = fmaf(fabsf(xj.y - xv), wf, acc[r][1]);
            acc[r][2] = fmaf(fabsf(xj.z - xv), wf, acc[r][2]);
            acc[r][3] = fmaf(fabsf(xj.w - xv), wf, acc[r][3]);
        }
    }

    const bool val0 = (j0 + 0) < len;
    const bool val1 = (j0 + 1) < len;
    const bool val2 = (j0 + 2) < len;
    const bool val3 = (j0 + 3) < len;

#pragma unroll
    for (int r = 0; r < R; r++) {
        const float s0 = acc[r][0], s1 = acc[r][1], s2 = acc[r][2], s3 = acc[r][3];
        const float t0 = (s0 < 1.0f) ? -s0 : 0.0f;
        const float t1 = (s1 < 1.0f) ? -s1 : 0.0f;
        const float t2 = (s2 < 1.0f) ? -s2 : 0.0f;
        const float t3 = (s3 < 1.0f) ? -s3 : 0.0f;

        // No max-pass: valid scores bounded in (-1, 0]; invalid -> exact 0.
        float4 e4;
        e4.x = __expf(val0 ? t0 : -1.0e9f);
        e4.y = __expf(val1 ? t1 : -1.0e9f);
        e4.z = __expf(val2 ? t2 : -1.0e9f);
        e4.w = __expf(val3 ? t3 : -1.0e9f);
        s_e[r][tid] = e4;                       // stage in smem, frees registers

        float ps = (e4.x + e4.y) + (e4.z + e4.w);
#pragma unroll
        for (int o = 16; o > 0; o >>= 1)
            ps += __shfl_xor_sync(0xFFFFFFFFu, ps, o);
        if (lane == 0) reds[r][wid] = ps;
    }
    __syncthreads();

#pragma unroll
    for (int r = 0; r < R; r++) {
        float t = reds[r][0];
#pragma unroll
        for (int k = 1; k < NW; k++) t += reds[r][k];
        const float inv = 1.0f / t;
        float4 e4 = s_e[r][tid];
        float4 o4;
        o4.x = e4.x * inv;
        o4.y = e4.y * inv;
        o4.z = e4.z * inv;
        o4.w = e4.w * inv;
        *reinterpret_cast<float4*>(out + ((size_t)(b * N_ + i0 + r)) * N_ + j0) = o4;
    }
}

extern "C" void kernel_launch(void* const* d_in, const int* in_sizes, int n_in,
                              void* d_out, int out_size)
{
    const float* x    = (const float*)d_in[0];
    const int*   xlen = (const int*)d_in[1];
    const float* fimp = (const float*)d_in[2];
    float*       out  = (float*)d_out;

    transpose_kernel<<<(BN + 255) / 256, 256>>>(x);
    dim3 grid(N_ / R, B_);
    featuresim_kernel<<<grid, BDIM>>>(xlen, fimp, out);
}